// round 1
// baseline (speedup 1.0000x reference)
#include <cuda_runtime.h>

#define NSP   2304          // 48*48 spatial positions
#define CH    512           // channels
#define BATCH 8

// ---------------- scratch (device globals; no allocations allowed) ----------
__device__ float g_tf[(size_t)BATCH * CH * NSP];
__device__ float g_Q [(size_t)BATCH * CH * NSP];
__device__ float g_K [(size_t)BATCH * CH * NSP];
__device__ float g_V [(size_t)BATCH * CH * NSP];
__device__ float g_S [(size_t)BATCH * NSP * NSP];   // attention scores / probs

// ============================================================================
// GEMM 1: Y[b] = W @ X[b] + bias      (W: [512,512] row-major, X: [512,2304])
// Classic 128x128x8 SGEMM, 256 threads, 8x8 per thread.
// ============================================================================
__global__ __launch_bounds__(256, 2)
void gemm_wx(const float* __restrict__ W, const float* __restrict__ Xall,
             const float* __restrict__ bias, float* __restrict__ Yall)
{
    __shared__ float As[8][132];   // A transposed in smem (padded)
    __shared__ float Bs[8][128];

    const int b  = blockIdx.z;
    const float* X = Xall + (size_t)b * CH * NSP;
    float*       Y = Yall + (size_t)b * CH * NSP;

    const int n0 = blockIdx.x * 128;
    const int m0 = blockIdx.y * 128;
    const int t  = threadIdx.x;
    const int tx = t & 15, ty = t >> 4;
    const int arow = t >> 1, acg = (t & 1) * 4;      // A tile: 128 rows x 8 k
    const int brow = t >> 5, bcol = (t & 31) * 4;    // B tile: 8 k x 128 cols

    float acc[8][8];
#pragma unroll
    for (int i = 0; i < 8; i++)
#pragma unroll
        for (int j = 0; j < 8; j++) acc[i][j] = 0.f;

    for (int k0 = 0; k0 < CH; k0 += 8) {
        float4 av = *(const float4*)&W[(size_t)(m0 + arow) * CH + k0 + acg];
        As[acg + 0][arow] = av.x;
        As[acg + 1][arow] = av.y;
        As[acg + 2][arow] = av.z;
        As[acg + 3][arow] = av.w;
        *(float4*)&Bs[brow][bcol] =
            *(const float4*)&X[(size_t)(k0 + brow) * NSP + n0 + bcol];
        __syncthreads();
#pragma unroll
        for (int kk = 0; kk < 8; kk++) {
            float a[8], bb[8];
#pragma unroll
            for (int i = 0; i < 8; i++) a[i]  = As[kk][ty * 8 + i];
#pragma unroll
            for (int j = 0; j < 8; j++) bb[j] = Bs[kk][tx * 8 + j];
#pragma unroll
            for (int i = 0; i < 8; i++)
#pragma unroll
                for (int j = 0; j < 8; j++) acc[i][j] += a[i] * bb[j];
        }
        __syncthreads();
    }

#pragma unroll
    for (int i = 0; i < 8; i++) {
        const int m = m0 + ty * 8 + i;
        const float bv = bias[m];
        float* yr = &Y[(size_t)m * NSP + n0 + tx * 8];
#pragma unroll
        for (int j = 0; j < 8; j++) yr[j] = acc[i][j] + bv;
    }
}

// ============================================================================
// GEMM 2 (TN): S[b][m][n] = scale * sum_k Q[b][k][m] * K[b][k][n]
// Both operand tiles load contiguous rows (k-major operands). m = query.
// ============================================================================
__global__ __launch_bounds__(256, 2)
void gemm_tn(const float* __restrict__ Qall, const float* __restrict__ Kall,
             const float* __restrict__ scale, float* __restrict__ Sall)
{
    __shared__ float As[8][128];
    __shared__ float Bs[8][128];

    const int b = blockIdx.z;
    const float* Q = Qall + (size_t)b * CH * NSP;
    const float* K = Kall + (size_t)b * CH * NSP;
    float*       S = Sall + (size_t)b * NSP * NSP;

    const int n0 = blockIdx.x * 128;
    const int m0 = blockIdx.y * 128;
    const int t  = threadIdx.x;
    const int tx = t & 15, ty = t >> 4;
    const int brow = t >> 5, bcol = (t & 31) * 4;

    float acc[8][8];
#pragma unroll
    for (int i = 0; i < 8; i++)
#pragma unroll
        for (int j = 0; j < 8; j++) acc[i][j] = 0.f;

    for (int k0 = 0; k0 < CH; k0 += 8) {
        *(float4*)&As[brow][bcol] =
            *(const float4*)&Q[(size_t)(k0 + brow) * NSP + m0 + bcol];
        *(float4*)&Bs[brow][bcol] =
            *(const float4*)&K[(size_t)(k0 + brow) * NSP + n0 + bcol];
        __syncthreads();
#pragma unroll
        for (int kk = 0; kk < 8; kk++) {
            float a[8], bb[8];
#pragma unroll
            for (int i = 0; i < 8; i++) a[i]  = As[kk][ty * 8 + i];
#pragma unroll
            for (int j = 0; j < 8; j++) bb[j] = Bs[kk][tx * 8 + j];
#pragma unroll
            for (int i = 0; i < 8; i++)
#pragma unroll
                for (int j = 0; j < 8; j++) acc[i][j] += a[i] * bb[j];
        }
        __syncthreads();
    }

    const float sc = *scale;
#pragma unroll
    for (int i = 0; i < 8; i++) {
        const int m = m0 + ty * 8 + i;
        float* sr = &S[(size_t)m * NSP + n0 + tx * 8];
#pragma unroll
        for (int j = 0; j < 8; j++) sr[j] = acc[i][j] * sc;
    }
}

// ============================================================================
// Row softmax over last dim (2304 = 9 * 256). One block per row.
// ============================================================================
__global__ void softmax_rows(float* __restrict__ S)
{
    __shared__ float red[256];
    float* r = S + (size_t)blockIdx.x * NSP;
    const int t = threadIdx.x;

    float v[9];
    float mx = -1e30f;
#pragma unroll
    for (int i = 0; i < 9; i++) {
        v[i] = r[t + i * 256];
        mx = fmaxf(mx, v[i]);
    }
    red[t] = mx;
    __syncthreads();
    for (int s = 128; s > 0; s >>= 1) {
        if (t < s) red[t] = fmaxf(red[t], red[t + s]);
        __syncthreads();
    }
    mx = red[0];
    __syncthreads();

    float sum = 0.f;
#pragma unroll
    for (int i = 0; i < 9; i++) {
        v[i] = __expf(v[i] - mx);
        sum += v[i];
    }
    red[t] = sum;
    __syncthreads();
    for (int s = 128; s > 0; s >>= 1) {
        if (t < s) red[t] += red[t + s];
        __syncthreads();
    }
    const float inv = 1.0f / red[0];
#pragma unroll
    for (int i = 0; i < 9; i++) r[t + i * 256] = v[i] * inv;
}

// ============================================================================
// GEMM 3 (NT): out[b][c][n] = img[b][c][n] + sum_m V[b][c][m] * P[b][n][m]
// Both operands contiguous along the reduction dim m -> transpose on smem store.
// ============================================================================
__global__ __launch_bounds__(256, 2)
void gemm_nt(const float* __restrict__ Vall, const float* __restrict__ Pall,
             const float* __restrict__ img, float* __restrict__ out)
{
    __shared__ float As[8][132];
    __shared__ float Bs[8][132];

    const int b = blockIdx.z;
    const float* V = Vall + (size_t)b * CH * NSP;
    const float* P = Pall + (size_t)b * NSP * NSP;
    const float* I = img  + (size_t)b * CH * NSP;
    float*       O = out  + (size_t)b * CH * NSP;

    const int n0 = blockIdx.x * 128;   // output spatial (query) tile
    const int c0 = blockIdx.y * 128;   // channel tile
    const int t  = threadIdx.x;
    const int tx = t & 15, ty = t >> 4;
    const int row = t >> 1, cg = (t & 1) * 4;   // 128 rows x 8 k, float4 per thread

    float acc[8][8];
#pragma unroll
    for (int i = 0; i < 8; i++)
#pragma unroll
        for (int j = 0; j < 8; j++) acc[i][j] = 0.f;

    for (int k0 = 0; k0 < NSP; k0 += 8) {
        float4 av = *(const float4*)&V[(size_t)(c0 + row) * NSP + k0 + cg];
        As[cg + 0][row] = av.x;
        As[cg + 1][row] = av.y;
        As[cg + 2][row] = av.z;
        As[cg + 3][row] = av.w;
        float4 bv = *(const float4*)&P[(size_t)(n0 + row) * NSP + k0 + cg];
        Bs[cg + 0][row] = bv.x;
        Bs[cg + 1][row] = bv.y;
        Bs[cg + 2][row] = bv.z;
        Bs[cg + 3][row] = bv.w;
        __syncthreads();
#pragma unroll
        for (int kk = 0; kk < 8; kk++) {
            float a[8], bb[8];
#pragma unroll
            for (int i = 0; i < 8; i++) a[i]  = As[kk][ty * 8 + i];
#pragma unroll
            for (int j = 0; j < 8; j++) bb[j] = Bs[kk][tx * 8 + j];
#pragma unroll
            for (int i = 0; i < 8; i++)
#pragma unroll
                for (int j = 0; j < 8; j++) acc[i][j] += a[i] * bb[j];
        }
        __syncthreads();
    }

#pragma unroll
    for (int i = 0; i < 8; i++) {
        const int c = c0 + ty * 8 + i;
        const float* ir = &I[(size_t)c * NSP + n0 + tx * 8];
        float*       orow = &O[(size_t)c * NSP + n0 + tx * 8];
#pragma unroll
        for (int j = 0; j < 8; j++) orow[j] = acc[i][j] + ir[j];
    }
}

// ============================================================================
// Launch
// ============================================================================
extern "C" void kernel_launch(void* const* d_in, const int* in_sizes, int n_in,
                              void* d_out, int out_size)
{
    const float* img   = (const float*)d_in[0];
    const float* text  = (const float*)d_in[1];
    const float* w_tp  = (const float*)d_in[2];
    const float* b_tp  = (const float*)d_in[3];
    const float* w_q   = (const float*)d_in[4];
    const float* b_q   = (const float*)d_in[5];
    const float* w_k   = (const float*)d_in[6];
    const float* b_k   = (const float*)d_in[7];
    const float* w_v   = (const float*)d_in[8];
    const float* b_v   = (const float*)d_in[9];
    const float* scale = (const float*)d_in[10];

    float *tf_p, *q_p, *k_p, *v_p, *s_p;
    cudaGetSymbolAddress((void**)&tf_p, g_tf);
    cudaGetSymbolAddress((void**)&q_p,  g_Q);
    cudaGetSymbolAddress((void**)&k_p,  g_K);
    cudaGetSymbolAddress((void**)&v_p,  g_V);
    cudaGetSymbolAddress((void**)&s_p,  g_S);

    dim3 blk(256);
    dim3 grid_wx(NSP / 128, CH / 128, BATCH);     // (18, 4, 8)
    dim3 grid_tn(NSP / 128, NSP / 128, BATCH);    // (18, 18, 8)

    gemm_wx<<<grid_wx, blk>>>(w_tp, text, b_tp, tf_p);     // tf
    gemm_wx<<<grid_wx, blk>>>(w_q,  img,  b_q,  q_p);      // Q
    gemm_wx<<<grid_wx, blk>>>(w_k,  tf_p, b_k,  k_p);      // K
    gemm_wx<<<grid_wx, blk>>>(w_v,  tf_p, b_v,  v_p);      // V
    gemm_tn<<<grid_tn, blk>>>(q_p, k_p, scale, s_p);       // S = scale * Q^T K
    softmax_rows<<<BATCH * NSP, 256>>>(s_p);               // P = softmax(S)
    gemm_nt<<<grid_wx, blk>>>(v_p, s_p, img, (float*)d_out); // out = V P^T + img
}

// round 3
// speedup vs baseline: 2.2427x; 2.2427x over previous
#include <cuda_runtime.h>
#include <cuda_fp16.h>

#define NSP   2304
#define CH    512
#define BATCH 8
#define BK    32
#define PAD   40      // halves per smem row (conflict-free fragment loads)

// ---------------- scratch (device globals; no allocations) ------------------
__device__ __half g_tT_hi [(size_t)BATCH * NSP * CH];  // text^T  [n][c]
__device__ __half g_tT_lo [(size_t)BATCH * NSP * CH];
__device__ __half g_iT_hi [(size_t)BATCH * NSP * CH];  // img^T   [n][c]
__device__ __half g_iT_lo [(size_t)BATCH * NSP * CH];
__device__ __half g_w_hi  [(size_t)4 * CH * CH];       // w_tp,w_q,w_k,w_v
__device__ __half g_w_lo  [(size_t)4 * CH * CH];
__device__ __half g_tfT_hi[(size_t)BATCH * NSP * CH];  // tf^T [n][c]
__device__ __half g_tfT_lo[(size_t)BATCH * NSP * CH];
__device__ __half g_qT_hi [(size_t)BATCH * NSP * CH];
__device__ __half g_qT_lo [(size_t)BATCH * NSP * CH];
__device__ __half g_kT_hi [(size_t)BATCH * NSP * CH];
__device__ __half g_kT_lo [(size_t)BATCH * NSP * CH];
__device__ __half g_v_hi  [(size_t)BATCH * CH * NSP];  // V [c][n]
__device__ __half g_v_lo  [(size_t)BATCH * CH * NSP];
__device__ float  g_S     [(size_t)BATCH * NSP * NSP];
__device__ __half g_P_hi  [(size_t)BATCH * NSP * NSP];
__device__ __half g_P_lo  [(size_t)BATCH * NSP * NSP];

// ---------------- helpers ----------------------------------------------------
__device__ __forceinline__ void split2(float f, __half& h, __half& l) {
    h = __float2half_rn(f);
    l = __float2half_rn(f - __half2float(h));
}

__device__ __forceinline__ void mma16816(float (&d)[4], const unsigned (&a)[4],
                                         const unsigned (&b)[2]) {
    asm volatile(
        "mma.sync.aligned.m16n8k16.row.col.f32.f16.f16.f32 "
        "{%0,%1,%2,%3}, {%4,%5,%6,%7}, {%8,%9}, {%0,%1,%2,%3};\n"
        : "+f"(d[0]), "+f"(d[1]), "+f"(d[2]), "+f"(d[3])
        : "r"(a[0]), "r"(a[1]), "r"(a[2]), "r"(a[3]), "r"(b[0]), "r"(b[1]));
}

// ---------------- pre-pass: transpose fp32 [C][N] -> split f16 [N][C] --------
__global__ void split_transpose(const float* __restrict__ in,
                                __half* __restrict__ ohi, __half* __restrict__ olo)
{
    __shared__ float tile[32][33];
    const int bz = blockIdx.z;
    const float* I = in  + (size_t)bz * CH * NSP;
    __half* H = ohi + (size_t)bz * NSP * CH;
    __half* L = olo + (size_t)bz * NSP * CH;
    const int n0 = blockIdx.x * 32, c0 = blockIdx.y * 32;
    const int tx = threadIdx.x, ty = threadIdx.y;   // (32, 8)
#pragma unroll
    for (int j = 0; j < 32; j += 8)
        tile[ty + j][tx] = I[(size_t)(c0 + ty + j) * NSP + n0 + tx];
    __syncthreads();
#pragma unroll
    for (int j = 0; j < 32; j += 8) {
        float f = tile[tx][ty + j];
        __half h, l; split2(f, h, l);
        size_t off = (size_t)(n0 + ty + j) * CH + c0 + tx;
        H[off] = h; L[off] = l;
    }
}

// ---------------- pre-pass: split the four weight matrices -------------------
__global__ void split_w(const float* __restrict__ w0, const float* __restrict__ w1,
                        const float* __restrict__ w2, const float* __restrict__ w3,
                        __half* __restrict__ hi, __half* __restrict__ lo)
{
    const int z = blockIdx.z;
    const float* w = (z == 0) ? w0 : (z == 1) ? w1 : (z == 2) ? w2 : w3;
    const int i = blockIdx.x * 256 + threadIdx.x;
    __half h, l; split2(w[i], h, l);
    hi[(size_t)z * CH * CH + i] = h;
    lo[(size_t)z * CH * CH + i] = l;
}

// ============================================================================
// Split-f16 NT HGEMM:  Y[m][n] = sum_k A[m][k] * B[n][k]   (A,B as hi+lo f16)
// EPI 0: +bias[n], write split f16     EPI 1: +bias[m], write split f16
// EPI 2: *(*aux),  write fp32          EPI 3: +res[m][n], write fp32
// ============================================================================
template<int EPI>
__global__ __launch_bounds__(256)
void hgemm_nt(const __half* __restrict__ Agh, const __half* __restrict__ Agl,
              const __half* __restrict__ Bgh, const __half* __restrict__ Bgl,
              const float* __restrict__ aux, const float* __restrict__ resg,
              float* __restrict__ Yfg, __half* __restrict__ Yhg, __half* __restrict__ Ylg,
              int K, int ldY, size_t strA, size_t strB, size_t strY)
{
    __shared__ __half sAh[128 * PAD], sAl[128 * PAD];
    __shared__ __half sBh[128 * PAD], sBl[128 * PAD];

    const int bz = blockIdx.z;
    const __half* Ah = Agh + strA * bz;
    const __half* Al = Agl + strA * bz;
    const __half* Bh = Bgh + strB * bz;
    const __half* Bl = Bgl + strB * bz;

    const int n0 = blockIdx.x * 128;
    const int m0 = blockIdx.y * 128;
    const int t    = threadIdx.x;
    const int lane = t & 31;
    const int warp = t >> 5;
    const int wm   = (warp & 3) * 32;
    const int wn   = (warp >> 2) * 64;
    const int grp  = lane >> 2;
    const int qid  = lane & 3;

    float acc[2][8][4];
#pragma unroll
    for (int mt = 0; mt < 2; mt++)
#pragma unroll
        for (int nt = 0; nt < 8; nt++)
#pragma unroll
            for (int r = 0; r < 4; r++) acc[mt][nt][r] = 0.f;

    for (int k0 = 0; k0 < K; k0 += BK) {
#pragma unroll
        for (int i = 0; i < 2; i++) {
            const int idx = t + 256 * i;          // 0..511
            const int kg = idx & 3, m = idx >> 2; // kg: 8-half group, m/n: 0..127
            const size_t ga = (size_t)(m0 + m) * K + k0 + kg * 8;
            const size_t gb = (size_t)(n0 + m) * K + k0 + kg * 8;
            *(uint4*)&sAh[m * PAD + kg * 8] = *(const uint4*)&Ah[ga];
            *(uint4*)&sAl[m * PAD + kg * 8] = *(const uint4*)&Al[ga];
            *(uint4*)&sBh[m * PAD + kg * 8] = *(const uint4*)&Bh[gb];
            *(uint4*)&sBl[m * PAD + kg * 8] = *(const uint4*)&Bl[gb];
        }
        __syncthreads();

#pragma unroll
        for (int ks = 0; ks < 2; ks++) {
            const int kb = ks * 16;
            unsigned ah[2][4], al[2][4];
#pragma unroll
            for (int mt = 0; mt < 2; mt++) {
                const int r0 = (wm + mt * 16 + grp) * PAD + kb + qid * 2;
                const int r1 = r0 + 8 * PAD;
                ah[mt][0] = *(const unsigned*)&sAh[r0];
                ah[mt][1] = *(const unsigned*)&sAh[r1];
                ah[mt][2] = *(const unsigned*)&sAh[r0 + 8];
                ah[mt][3] = *(const unsigned*)&sAh[r1 + 8];
                al[mt][0] = *(const unsigned*)&sAl[r0];
                al[mt][1] = *(const unsigned*)&sAl[r1];
                al[mt][2] = *(const unsigned*)&sAl[r0 + 8];
                al[mt][3] = *(const unsigned*)&sAl[r1 + 8];
            }
#pragma unroll
            for (int nt = 0; nt < 8; nt++) {
                const int c0i = (wn + nt * 8 + grp) * PAD + kb + qid * 2;
                unsigned bh[2], bl[2];
                bh[0] = *(const unsigned*)&sBh[c0i];
                bh[1] = *(const unsigned*)&sBh[c0i + 8];
                bl[0] = *(const unsigned*)&sBl[c0i];
                bl[1] = *(const unsigned*)&sBl[c0i + 8];
#pragma unroll
                for (int mt = 0; mt < 2; mt++) {
                    mma16816(acc[mt][nt], ah[mt], bh);   // hi*hi
                    mma16816(acc[mt][nt], ah[mt], bl);   // hi*lo
                    mma16816(acc[mt][nt], al[mt], bh);   // lo*hi
                }
            }
        }
        __syncthreads();
    }

    // ---- epilogue ----
    const float* res = (EPI == 3) ? (resg + strY * bz) : nullptr;
    float* Yf  = (EPI >= 2) ? (Yfg + strY * bz) : nullptr;
    __half* Yh = (EPI < 2) ? (Yhg + strY * bz) : nullptr;
    __half* Yl = (EPI < 2) ? (Ylg + strY * bz) : nullptr;
    const float sc = (EPI == 2) ? *aux : 0.f;

#pragma unroll
    for (int mt = 0; mt < 2; mt++)
#pragma unroll
        for (int r2 = 0; r2 < 2; r2++) {
            const int m = m0 + wm + mt * 16 + grp + 8 * r2;
            const float bvr = (EPI == 1) ? aux[m] : 0.f;
#pragma unroll
            for (int nt = 0; nt < 8; nt++) {
                const int n = n0 + wn + nt * 8 + qid * 2;
                float v0 = acc[mt][nt][r2 * 2 + 0];
                float v1 = acc[mt][nt][r2 * 2 + 1];
                if (EPI == 0) { v0 += aux[n]; v1 += aux[n + 1]; }
                if (EPI == 1) { v0 += bvr;    v1 += bvr; }
                if (EPI == 2) { v0 *= sc;     v1 *= sc; }
                const size_t off = (size_t)m * ldY + n;
                if (EPI == 3) { v0 += res[off]; v1 += res[off + 1]; }
                if (EPI >= 2) {
                    *(float2*)&Yf[off] = make_float2(v0, v1);
                } else {
                    __half h0, l0, h1, l1;
                    split2(v0, h0, l0); split2(v1, h1, l1);
                    *(__half2*)&Yh[off] = __halves2half2(h0, h1);
                    *(__half2*)&Yl[off] = __halves2half2(l0, l1);
                }
            }
        }
}

// ---------------- softmax over rows of S, emit split-f16 P -------------------
__global__ void softmax_split(const float* __restrict__ S,
                              __half* __restrict__ Ph, __half* __restrict__ Pl)
{
    __shared__ float red[256];
    const size_t ro = (size_t)blockIdx.x * NSP;
    const float* r = S + ro;
    const int t = threadIdx.x;

    float v[9];
    float mx = -1e30f;
#pragma unroll
    for (int i = 0; i < 9; i++) {
        v[i] = r[t + i * 256];
        mx = fmaxf(mx, v[i]);
    }
    red[t] = mx;
    __syncthreads();
    for (int s = 128; s > 0; s >>= 1) {
        if (t < s) red[t] = fmaxf(red[t], red[t + s]);
        __syncthreads();
    }
    mx = red[0];
    __syncthreads();

    float sum = 0.f;
#pragma unroll
    for (int i = 0; i < 9; i++) {
        v[i] = __expf(v[i] - mx);
        sum += v[i];
    }
    red[t] = sum;
    __syncthreads();
    for (int s = 128; s > 0; s >>= 1) {
        if (t < s) red[t] += red[t + s];
        __syncthreads();
    }
    const float inv = 1.0f / red[0];
#pragma unroll
    for (int i = 0; i < 9; i++) {
        const float p = v[i] * inv;
        __half h, l; split2(p, h, l);
        Ph[ro + t + i * 256] = h;
        Pl[ro + t + i * 256] = l;
    }
}

// ============================================================================
// Launch
// ============================================================================
extern "C" void kernel_launch(void* const* d_in, const int* in_sizes, int n_in,
                              void* d_out, int out_size)
{
    const float* img   = (const float*)d_in[0];
    const float* text  = (const float*)d_in[1];
    const float* w_tp  = (const float*)d_in[2];
    const float* b_tp  = (const float*)d_in[3];
    const float* w_q   = (const float*)d_in[4];
    const float* b_q   = (const float*)d_in[5];
    const float* w_k   = (const float*)d_in[6];
    const float* b_k   = (const float*)d_in[7];
    const float* w_v   = (const float*)d_in[8];
    const float* b_v   = (const float*)d_in[9];
    const float* scale = (const float*)d_in[10];

    __half *tTh, *tTl, *iTh, *iTl, *wh, *wl, *tfh, *tfl, *qh, *ql, *kh, *kl, *vh, *vl, *ph, *pl;
    float* sp;
    cudaGetSymbolAddress((void**)&tTh, g_tT_hi);  cudaGetSymbolAddress((void**)&tTl, g_tT_lo);
    cudaGetSymbolAddress((void**)&iTh, g_iT_hi);  cudaGetSymbolAddress((void**)&iTl, g_iT_lo);
    cudaGetSymbolAddress((void**)&wh,  g_w_hi);   cudaGetSymbolAddress((void**)&wl,  g_w_lo);
    cudaGetSymbolAddress((void**)&tfh, g_tfT_hi); cudaGetSymbolAddress((void**)&tfl, g_tfT_lo);
    cudaGetSymbolAddress((void**)&qh,  g_qT_hi);  cudaGetSymbolAddress((void**)&ql,  g_qT_lo);
    cudaGetSymbolAddress((void**)&kh,  g_kT_hi);  cudaGetSymbolAddress((void**)&kl,  g_kT_lo);
    cudaGetSymbolAddress((void**)&vh,  g_v_hi);   cudaGetSymbolAddress((void**)&vl,  g_v_lo);
    cudaGetSymbolAddress((void**)&ph,  g_P_hi);   cudaGetSymbolAddress((void**)&pl,  g_P_lo);
    cudaGetSymbolAddress((void**)&sp,  g_S);

    const size_t sNC = (size_t)NSP * CH;   // per-batch stride of [n][c] / [c][n]
    const size_t sNN = (size_t)NSP * NSP;
    const size_t sW  = (size_t)CH * CH;

    dim3 tb(32, 8);
    dim3 tg(NSP / 32, CH / 32, BATCH);     // (72, 16, 8)
    split_transpose<<<tg, tb>>>(text, tTh, tTl);
    split_transpose<<<tg, tb>>>(img,  iTh, iTl);
    split_w<<<dim3(CH * CH / 256, 1, 4), 256>>>(w_tp, w_q, w_k, w_v, wh, wl);

    dim3 blk(256);
    dim3 grid_p (CH / 128, NSP / 128, BATCH);   // (4, 18, 8)  M=NSP, N=CH
    dim3 grid_v (NSP / 128, CH / 128, BATCH);   // (18, 4, 8)  M=CH, N=NSP
    dim3 grid_s (NSP / 128, NSP / 128, BATCH);  // (18, 18, 8)

    // tfT[n][o] = text^T @ w_tp^T + b_tp[o]
    hgemm_nt<0><<<grid_p, blk>>>(tTh, tTl, wh + 0 * sW, wl + 0 * sW, b_tp, nullptr,
                                 nullptr, tfh, tfl, CH, CH, sNC, 0, sNC);
    // QT[n][o] = img^T @ w_q^T + b_q[o]
    hgemm_nt<0><<<grid_p, blk>>>(iTh, iTl, wh + 1 * sW, wl + 1 * sW, b_q, nullptr,
                                 nullptr, qh, ql, CH, CH, sNC, 0, sNC);
    // KT[n][o] = tfT @ w_k^T + b_k[o]
    hgemm_nt<0><<<grid_p, blk>>>(tfh, tfl, wh + 2 * sW, wl + 2 * sW, b_k, nullptr,
                                 nullptr, kh, kl, CH, CH, sNC, 0, sNC);
    // V[o][n] = w_v @ tf + b_v[o]   (A = w_v, B = tfT)
    hgemm_nt<1><<<grid_v, blk>>>(wh + 3 * sW, wl + 3 * sW, tfh, tfl, b_v, nullptr,
                                 nullptr, vh, vl, CH, NSP, 0, sNC, sNC);
    // S[nq][nk] = scale * QT @ KT^T
    hgemm_nt<2><<<grid_s, blk>>>(qh, ql, kh, kl, scale, nullptr,
                                 sp, nullptr, nullptr, CH, NSP, sNC, sNC, sNN);
    // P = softmax(S), split
    softmax_split<<<BATCH * NSP, 256>>>(sp, ph, pl);
    // out[c][n] = img[c][n] + V @ P^T
    hgemm_nt<3><<<grid_v, blk>>>(vh, vl, ph, pl, nullptr, img,
                                 (float*)d_out, nullptr, nullptr, NSP, NSP, sNC, sNN, sNC);
}

// round 5
// speedup vs baseline: 2.7641x; 1.2324x over previous
#include <cuda_runtime.h>
#include <cuda_fp16.h>
#include <cstdint>

#define NSP   2304
#define CH    512
#define BATCH 8
#define BK    32
#define PAD   40                       // halves per smem row (16B-aligned, conflict-free)
#define MAT_B (128 * PAD * 2)          // 10240 bytes per matrix tile
#define STG_B (4 * MAT_B)              // Ah, Al, Bh, Bl = 40960 bytes
#define SMEM_TOTAL (2 * STG_B)         // 81920 bytes, double-buffered

// ---------------- scratch (device globals; no allocations) ------------------
__device__ __half g_tT_hi [(size_t)BATCH * NSP * CH];
__device__ __half g_tT_lo [(size_t)BATCH * NSP * CH];
__device__ __half g_iT_hi [(size_t)BATCH * NSP * CH];
__device__ __half g_iT_lo [(size_t)BATCH * NSP * CH];
__device__ __half g_w_hi  [(size_t)4 * CH * CH];
__device__ __half g_w_lo  [(size_t)4 * CH * CH];
__device__ __half g_tfT_hi[(size_t)BATCH * NSP * CH];
__device__ __half g_tfT_lo[(size_t)BATCH * NSP * CH];
__device__ __half g_qT_hi [(size_t)BATCH * NSP * CH];
__device__ __half g_qT_lo [(size_t)BATCH * NSP * CH];
__device__ __half g_kT_hi [(size_t)BATCH * NSP * CH];
__device__ __half g_kT_lo [(size_t)BATCH * NSP * CH];
__device__ __half g_v_hi  [(size_t)BATCH * CH * NSP];
__device__ __half g_v_lo  [(size_t)BATCH * CH * NSP];
__device__ float  g_S     [(size_t)BATCH * NSP * NSP];
__device__ __half g_P_hi  [(size_t)BATCH * NSP * NSP];
__device__ __half g_P_lo  [(size_t)BATCH * NSP * NSP];

// ---------------- helpers ----------------------------------------------------
__device__ __forceinline__ uint32_t smem_u32(const void* p) {
    uint32_t a;
    asm("{ .reg .u64 t; cvta.to.shared.u64 t, %1; cvt.u32.u64 %0, t; }" : "=r"(a) : "l"(p));
    return a;
}
__device__ __forceinline__ void cp16(uint32_t saddr, const void* g) {
    asm volatile("cp.async.cg.shared.global [%0], [%1], 16;\n" :: "r"(saddr), "l"(g));
}
__device__ __forceinline__ void cp_commit() { asm volatile("cp.async.commit_group;\n"); }
template<int N> __device__ __forceinline__ void cp_wait() {
    asm volatile("cp.async.wait_group %0;\n" :: "n"(N));
}
__device__ __forceinline__ void ldsm4(unsigned (&r)[4], uint32_t addr) {
    asm volatile("ldmatrix.sync.aligned.m8n8.x4.shared.b16 {%0,%1,%2,%3}, [%4];"
        : "=r"(r[0]), "=r"(r[1]), "=r"(r[2]), "=r"(r[3]) : "r"(addr));
}
__device__ __forceinline__ void mma16816(float (&d)[4], const unsigned (&a)[4],
                                         unsigned b0, unsigned b1) {
    asm volatile(
        "mma.sync.aligned.m16n8k16.row.col.f32.f16.f16.f32 "
        "{%0,%1,%2,%3}, {%4,%5,%6,%7}, {%8,%9}, {%0,%1,%2,%3};\n"
        : "+f"(d[0]), "+f"(d[1]), "+f"(d[2]), "+f"(d[3])
        : "r"(a[0]), "r"(a[1]), "r"(a[2]), "r"(a[3]), "r"(b0), "r"(b1));
}
__device__ __forceinline__ void split2(float f, __half& h, __half& l) {
    h = __float2half_rn(f);
    l = __float2half_rn(f - __half2float(h));
}

// ---------------- pre-pass: transpose fp32 [C][N] -> split f16 [N][C] --------
__global__ void split_transpose(const float* __restrict__ in,
                                __half* __restrict__ ohi, __half* __restrict__ olo)
{
    __shared__ float tile[32][33];
    const int bz = blockIdx.z;
    const float* I = in  + (size_t)bz * CH * NSP;
    __half* H = ohi + (size_t)bz * NSP * CH;
    __half* L = olo + (size_t)bz * NSP * CH;
    const int n0 = blockIdx.x * 32, c0 = blockIdx.y * 32;
    const int tx = threadIdx.x, ty = threadIdx.y;
#pragma unroll
    for (int j = 0; j < 32; j += 8)
        tile[ty + j][tx] = I[(size_t)(c0 + ty + j) * NSP + n0 + tx];
    __syncthreads();
#pragma unroll
    for (int j = 0; j < 32; j += 8) {
        float f = tile[tx][ty + j];
        __half h, l; split2(f, h, l);
        size_t off = (size_t)(n0 + ty + j) * CH + c0 + tx;
        H[off] = h; L[off] = l;
    }
}

__global__ void split_w(const float* __restrict__ w0, const float* __restrict__ w1,
                        const float* __restrict__ w2, const float* __restrict__ w3,
                        __half* __restrict__ hi, __half* __restrict__ lo)
{
    const int z = blockIdx.z;
    const float* w = (z == 0) ? w0 : (z == 1) ? w1 : (z == 2) ? w2 : w3;
    const int i = blockIdx.x * 256 + threadIdx.x;
    __half h, l; split2(w[i], h, l);
    hi[(size_t)z * CH * CH + i] = h;
    lo[(size_t)z * CH * CH + i] = l;
}

// ============================================================================
// Split-f16 NT HGEMM, cp.async double-buffered, ldmatrix fragment loads.
//   Y[m][n] = sum_k A[m][k] * B[n][k]   (A,B as hi+lo f16, row stride = K)
// EPI 0: +bias[n] -> split f16 | 1: +bias[m] -> split f16
// EPI 2: *(*aux)  -> fp32      | 3: +res     -> fp32
// ============================================================================
template<int EPI>
__global__ __launch_bounds__(256, 2)
void hgemm_nt(const __half* __restrict__ Agh, const __half* __restrict__ Agl,
              const __half* __restrict__ Bgh, const __half* __restrict__ Bgl,
              const float* __restrict__ aux, const float* __restrict__ resg,
              float* __restrict__ Yfg, __half* __restrict__ Yhg, __half* __restrict__ Ylg,
              int K, int ldY, size_t strA, size_t strB, size_t strY)
{
    extern __shared__ char smem[];
    const uint32_t sb = smem_u32(smem);

    const int bz = blockIdx.z;
    const __half* Ah = Agh + strA * bz;
    const __half* Al = Agl + strA * bz;
    const __half* Bh = Bgh + strB * bz;
    const __half* Bl = Bgl + strB * bz;

    const int n0 = blockIdx.x * 128;
    const int m0 = blockIdx.y * 128;
    const int t    = threadIdx.x;
    const int lane = t & 31;
    const int warp = t >> 5;
    const int wm   = (warp & 3) * 32;
    const int wn   = (warp >> 2) * 64;
    const int grp  = lane >> 2;
    const int qid  = lane & 3;

    // ldmatrix per-lane byte offsets within a matrix tile
    const uint32_t offA = (uint32_t)(wm + (lane & 15)) * (PAD * 2) + (lane >> 4) * 16;
    const uint32_t offB = (uint32_t)(wn + ((lane >> 4) & 1) * 8 + (lane & 7)) * (PAD * 2)
                        + ((lane >> 3) & 1) * 16;

    float acc[2][8][4];
#pragma unroll
    for (int mt = 0; mt < 2; mt++)
#pragma unroll
        for (int nt = 0; nt < 8; nt++)
#pragma unroll
            for (int r = 0; r < 4; r++) acc[mt][nt][r] = 0.f;

    auto load_chunk = [&](int c) {
        const int k0 = c * BK;
        const uint32_t so = sb + (c & 1) * STG_B;
        const __half* srcs[4] = { Ah, Al, Bh, Bl };
#pragma unroll
        for (int mat = 0; mat < 4; mat++) {
            const __half* S = srcs[mat];
            const int base = (mat < 2) ? m0 : n0;
#pragma unroll
            for (int i = 0; i < 2; i++) {
                const int idx = t + 256 * i;
                const int kg = idx & 3, r = idx >> 2;
                cp16(so + mat * MAT_B + r * (PAD * 2) + kg * 16,
                     &S[(size_t)(base + r) * K + k0 + kg * 8]);
            }
        }
        cp_commit();
    };

    const int nch = K / BK;
    load_chunk(0);
    load_chunk(1);

    for (int c = 0; c < nch; c++) {
        if (c + 1 < nch) cp_wait<1>(); else cp_wait<0>();
        __syncthreads();

        const uint32_t stg = sb + (c & 1) * STG_B;
        const uint32_t aHb = stg;
        const uint32_t aLb = stg + MAT_B;
        const uint32_t bHb = stg + 2 * MAT_B;
        const uint32_t bLb = stg + 3 * MAT_B;

#pragma unroll
        for (int ks = 0; ks < 2; ks++) {
            const uint32_t kb2 = ks * 32;   // 16 halves = 32 bytes
            unsigned ah[2][4], al[2][4];
            ldsm4(ah[0], aHb + offA + kb2);
            ldsm4(ah[1], aHb + offA + 16 * (PAD * 2) + kb2);
            ldsm4(al[0], aLb + offA + kb2);
            ldsm4(al[1], aLb + offA + 16 * (PAD * 2) + kb2);
#pragma unroll
            for (int np = 0; np < 4; np++) {
                unsigned bh[4], bl[4];
                ldsm4(bh, bHb + offB + np * 16 * (PAD * 2) + kb2);
                ldsm4(bl, bLb + offB + np * 16 * (PAD * 2) + kb2);
#pragma unroll
                for (int mt = 0; mt < 2; mt++) {
                    mma16816(acc[mt][2 * np],     ah[mt], bh[0], bh[1]);
                    mma16816(acc[mt][2 * np],     ah[mt], bl[0], bl[1]);
                    mma16816(acc[mt][2 * np],     al[mt], bh[0], bh[1]);
                    mma16816(acc[mt][2 * np + 1], ah[mt], bh[2], bh[3]);
                    mma16816(acc[mt][2 * np + 1], ah[mt], bl[2], bl[3]);
                    mma16816(acc[mt][2 * np + 1], al[mt], bh[2], bh[3]);
                }
            }
        }
        __syncthreads();
        if (c + 2 < nch) load_chunk(c + 2);
    }

    // ---- epilogue (same mapping as R3) ----
    const float* res = (EPI == 3) ? (resg + strY * bz) : nullptr;
    float* Yf  = (EPI >= 2) ? (Yfg + strY * bz) : nullptr;
    __half* Yh = (EPI < 2) ? (Yhg + strY * bz) : nullptr;
    __half* Yl = (EPI < 2) ? (Ylg + strY * bz) : nullptr;
    const float sc = (EPI == 2) ? *aux : 0.f;

#pragma unroll
    for (int mt = 0; mt < 2; mt++)
#pragma unroll
        for (int r2 = 0; r2 < 2; r2++) {
            const int m = m0 + wm + mt * 16 + grp + 8 * r2;
            const float bvr = (EPI == 1) ? aux[m] : 0.f;
#pragma unroll
            for (int nt = 0; nt < 8; nt++) {
                const int n = n0 + wn + nt * 8 + qid * 2;
                float v0 = acc[mt][nt][r2 * 2 + 0];
                float v1 = acc[mt][nt][r2 * 2 + 1];
                if (EPI == 0) { v0 += aux[n]; v1 += aux[n + 1]; }
                if (EPI == 1) { v0 += bvr;    v1 += bvr; }
                if (EPI == 2) { v0 *= sc;     v1 *= sc; }
                const size_t off = (size_t)m * ldY + n;
                if (EPI == 3) { v0 += res[off]; v1 += res[off + 1]; }
                if (EPI >= 2) {
                    *(float2*)&Yf[off] = make_float2(v0, v1);
                } else {
                    __half h0, l0, h1, l1;
                    split2(v0, h0, l0); split2(v1, h1, l1);
                    *(__half2*)&Yh[off] = __halves2half2(h0, h1);
                    *(__half2*)&Yl[off] = __halves2half2(l0, l1);
                }
            }
        }
}

// ---------------- softmax over rows of S, emit split-f16 P -------------------
__global__ void softmax_split(const float* __restrict__ S,
                              __half* __restrict__ Ph, __half* __restrict__ Pl)
{
    __shared__ float red[256];
    const size_t ro = (size_t)blockIdx.x * NSP;
    const float* r = S + ro;
    const int t = threadIdx.x;

    float v[9];
    float mx = -1e30f;
#pragma unroll
    for (int i = 0; i < 9; i++) { v[i] = r[t + i * 256]; mx = fmaxf(mx, v[i]); }
    red[t] = mx;
    __syncthreads();
    for (int s = 128; s > 0; s >>= 1) {
        if (t < s) red[t] = fmaxf(red[t], red[t + s]);
        __syncthreads();
    }
    mx = red[0];
    __syncthreads();
    float sum = 0.f;
#pragma unroll
    for (int i = 0; i < 9; i++) { v[i] = __expf(v[i] - mx); sum += v[i]; }
    red[t] = sum;
    __syncthreads();
    for (int s = 128; s > 0; s >>= 1) {
        if (t < s) red[t] += red[t + s];
        __syncthreads();
    }
    const float inv = 1.0f / red[0];
#pragma unroll
    for (int i = 0; i < 9; i++) {
        __half h, l; split2(v[i] * inv, h, l);
        Ph[ro + t + i * 256] = h;
        Pl[ro + t + i * 256] = l;
    }
}

// ============================================================================
// Launch
// ============================================================================
extern "C" void kernel_launch(void* const* d_in, const int* in_sizes, int n_in,
                              void* d_out, int out_size)
{
    const float* img   = (const float*)d_in[0];
    const float* text  = (const float*)d_in[1];
    const float* w_tp  = (const float*)d_in[2];
    const float* b_tp  = (const float*)d_in[3];
    const float* w_q   = (const float*)d_in[4];
    const float* b_q   = (const float*)d_in[5];
    const float* w_k   = (const float*)d_in[6];
    const float* b_k   = (const float*)d_in[7];
    const float* w_v   = (const float*)d_in[8];
    const float* b_v   = (const float*)d_in[9];
    const float* scale = (const float*)d_in[10];

    __half *tTh, *tTl, *iTh, *iTl, *wh, *wl, *tfh, *tfl, *qh, *ql, *kh, *kl, *vh, *vl, *ph, *pl;
    float* sp;
    cudaGetSymbolAddress((void**)&tTh, g_tT_hi);  cudaGetSymbolAddress((void**)&tTl, g_tT_lo);
    cudaGetSymbolAddress((void**)&iTh, g_iT_hi);  cudaGetSymbolAddress((void**)&iTl, g_iT_lo);
    cudaGetSymbolAddress((void**)&wh,  g_w_hi);   cudaGetSymbolAddress((void**)&wl,  g_w_lo);
    cudaGetSymbolAddress((void**)&tfh, g_tfT_hi); cudaGetSymbolAddress((void**)&tfl, g_tfT_lo);
    cudaGetSymbolAddress((void**)&qh,  g_qT_hi);  cudaGetSymbolAddress((void**)&ql,  g_qT_lo);
    cudaGetSymbolAddress((void**)&kh,  g_kT_hi);  cudaGetSymbolAddress((void**)&kl,  g_kT_lo);
    cudaGetSymbolAddress((void**)&vh,  g_v_hi);   cudaGetSymbolAddress((void**)&vl,  g_v_lo);
    cudaGetSymbolAddress((void**)&ph,  g_P_hi);   cudaGetSymbolAddress((void**)&pl,  g_P_lo);
    cudaGetSymbolAddress((void**)&sp,  g_S);

    cudaFuncSetAttribute(hgemm_nt<0>, cudaFuncAttributeMaxDynamicSharedMemorySize, SMEM_TOTAL);
    cudaFuncSetAttribute(hgemm_nt<1>, cudaFuncAttributeMaxDynamicSharedMemorySize, SMEM_TOTAL);
    cudaFuncSetAttribute(hgemm_nt<2>, cudaFuncAttributeMaxDynamicSharedMemorySize, SMEM_TOTAL);
    cudaFuncSetAttribute(hgemm_nt<3>, cudaFuncAttributeMaxDynamicSharedMemorySize, SMEM_TOTAL);

    const size_t sNC = (size_t)NSP * CH;
    const size_t sNN = (size_t)NSP * NSP;
    const size_t sW  = (size_t)CH * CH;

    dim3 tb(32, 8);
    dim3 tg(NSP / 32, CH / 32, BATCH);
    split_transpose<<<tg, tb>>>(text, tTh, tTl);
    split_transpose<<<tg, tb>>>(img,  iTh, iTl);
    split_w<<<dim3(CH * CH / 256, 1, 4), 256>>>(w_tp, w_q, w_k, w_v, wh, wl);

    dim3 blk(256);
    dim3 grid_p (CH / 128, NSP / 128, BATCH);   // M=NSP, N=CH
    dim3 grid_v (NSP / 128, CH / 128, BATCH);   // M=CH,  N=NSP
    dim3 grid_s (NSP / 128, NSP / 128, BATCH);  // M=NSP, N=NSP

    // tfT[n][o] = text^T @ w_tp^T + b_tp
    hgemm_nt<0><<<grid_p, blk, SMEM_TOTAL>>>(tTh, tTl, wh, wl, b_tp, nullptr,
                                             nullptr, tfh, tfl, CH, CH, sNC, 0, sNC);
    // QT[n][o] = img^T @ w_q^T + b_q
    hgemm_nt<0><<<grid_p, blk, SMEM_TOTAL>>>(iTh, iTl, wh + sW, wl + sW, b_q, nullptr,
                                             nullptr, qh, ql, CH, CH, sNC, 0, sNC);
    // KT[n][o] = tfT @ w_k^T + b_k
    hgemm_nt<0><<<grid_p, blk, SMEM_TOTAL>>>(tfh, tfl, wh + 2 * sW, wl + 2 * sW, b_k, nullptr,
                                             nullptr, kh, kl, CH, CH, sNC, 0, sNC);
    // V[o][n] = w_v @ tf + b_v
    hgemm_nt<1><<<grid_v, blk, SMEM_TOTAL>>>(wh + 3 * sW, wl + 3 * sW, tfh, tfl, b_v, nullptr,
                                             nullptr, vh, vl, CH, NSP, 0, sNC, sNC);
    // S = scale * QT @ KT^T
    hgemm_nt<2><<<grid_s, blk, SMEM_TOTAL>>>(qh, ql, kh, kl, scale, nullptr,
                                             sp, nullptr, nullptr, CH, NSP, sNC, sNC, sNN);
    // P = softmax(S)
    softmax_split<<<BATCH * NSP, 256>>>(sp, ph, pl);
    // out = V @ P^T + img
    hgemm_nt<3><<<grid_v, blk, SMEM_TOTAL>>>(vh, vl, ph, pl, nullptr, img,
                                             (float*)d_out, nullptr, nullptr,
                                             NSP, NSP, sNC, sNN, sNC);
}

// round 6
// speedup vs baseline: 2.7672x; 1.0011x over previous
#include <cuda_runtime.h>
#include <cuda_fp16.h>
#include <cstdint>

#define NSP   2304
#define CH    512
#define BATCH 8
#define BK    32
#define PAD   40                       // halves per smem row (16B-aligned, conflict-free)
#define MAT_B (128 * PAD * 2)          // 10240 bytes per matrix tile
#define STG_B (4 * MAT_B)              // Ah, Al, Bh, Bl = 40960 bytes
#define SMEM_TOTAL (2 * STG_B)         // 81920 bytes, double-buffered

// ---------------- scratch (device globals; no allocations) ------------------
__device__ __half g_tT_hi [(size_t)BATCH * NSP * CH];
__device__ __half g_tT_lo [(size_t)BATCH * NSP * CH];
__device__ __half g_iT_hi [(size_t)BATCH * NSP * CH];
__device__ __half g_iT_lo [(size_t)BATCH * NSP * CH];
__device__ __half g_w_hi  [(size_t)4 * CH * CH];
__device__ __half g_w_lo  [(size_t)4 * CH * CH];
__device__ __half g_tfT_hi[(size_t)BATCH * NSP * CH];
__device__ __half g_tfT_lo[(size_t)BATCH * NSP * CH];
__device__ __half g_qT_hi [(size_t)BATCH * NSP * CH];
__device__ __half g_qT_lo [(size_t)BATCH * NSP * CH];
__device__ __half g_kT_hi [(size_t)BATCH * NSP * CH];
__device__ __half g_kT_lo [(size_t)BATCH * NSP * CH];
__device__ __half g_v_hi  [(size_t)BATCH * CH * NSP];
__device__ __half g_v_lo  [(size_t)BATCH * CH * NSP];
__device__ float  g_S     [(size_t)BATCH * NSP * NSP];
__device__ __half g_P_hi  [(size_t)BATCH * NSP * NSP];
__device__ __half g_P_lo  [(size_t)BATCH * NSP * NSP];

// ---------------- helpers ----------------------------------------------------
__device__ __forceinline__ uint32_t smem_u32(const void* p) {
    uint32_t a;
    asm("{ .reg .u64 t; cvta.to.shared.u64 t, %1; cvt.u32.u64 %0, t; }" : "=r"(a) : "l"(p));
    return a;
}
__device__ __forceinline__ void cp16(uint32_t saddr, const void* g) {
    asm volatile("cp.async.cg.shared.global [%0], [%1], 16;\n" :: "r"(saddr), "l"(g));
}
__device__ __forceinline__ void cp_commit() { asm volatile("cp.async.commit_group;\n"); }
template<int N> __device__ __forceinline__ void cp_wait() {
    asm volatile("cp.async.wait_group %0;\n" :: "n"(N));
}
__device__ __forceinline__ void ldsm4(unsigned (&r)[4], uint32_t addr) {
    asm volatile("ldmatrix.sync.aligned.m8n8.x4.shared.b16 {%0,%1,%2,%3}, [%4];"
        : "=r"(r[0]), "=r"(r[1]), "=r"(r[2]), "=r"(r[3]) : "r"(addr));
}
__device__ __forceinline__ void mma16816(float (&d)[4], const unsigned (&a)[4],
                                         unsigned b0, unsigned b1) {
    asm volatile(
        "mma.sync.aligned.m16n8k16.row.col.f32.f16.f16.f32 "
        "{%0,%1,%2,%3}, {%4,%5,%6,%7}, {%8,%9}, {%0,%1,%2,%3};\n"
        : "+f"(d[0]), "+f"(d[1]), "+f"(d[2]), "+f"(d[3])
        : "r"(a[0]), "r"(a[1]), "r"(a[2]), "r"(a[3]), "r"(b0), "r"(b1));
}
__device__ __forceinline__ void split2(float f, __half& h, __half& l) {
    h = __float2half_rn(f);
    l = __float2half_rn(f - __half2float(h));
}

// ---------------- pre-pass: transpose fp32 [C][N] -> split f16 [N][C] --------
__global__ void split_transpose(const float* __restrict__ in,
                                __half* __restrict__ ohi, __half* __restrict__ olo)
{
    __shared__ float tile[32][33];
    const int bz = blockIdx.z;
    const float* I = in  + (size_t)bz * CH * NSP;
    __half* H = ohi + (size_t)bz * NSP * CH;
    __half* L = olo + (size_t)bz * NSP * CH;
    const int n0 = blockIdx.x * 32, c0 = blockIdx.y * 32;
    const int tx = threadIdx.x, ty = threadIdx.y;
#pragma unroll
    for (int j = 0; j < 32; j += 8)
        tile[ty + j][tx] = I[(size_t)(c0 + ty + j) * NSP + n0 + tx];
    __syncthreads();
#pragma unroll
    for (int j = 0; j < 32; j += 8) {
        float f = tile[tx][ty + j];
        __half h, l; split2(f, h, l);
        size_t off = (size_t)(n0 + ty + j) * CH + c0 + tx;
        H[off] = h; L[off] = l;
    }
}

__global__ void split_w(const float* __restrict__ w0, const float* __restrict__ w1,
                        const float* __restrict__ w2, const float* __restrict__ w3,
                        __half* __restrict__ hi, __half* __restrict__ lo)
{
    const int z = blockIdx.z;
    const float* w = (z == 0) ? w0 : (z == 1) ? w1 : (z == 2) ? w2 : w3;
    const int i = blockIdx.x * 256 + threadIdx.x;
    __half h, l; split2(w[i], h, l);
    hi[(size_t)z * CH * CH + i] = h;
    lo[(size_t)z * CH * CH + i] = l;
}

// ============================================================================
// Split-f16 NT HGEMM, cp.async double-buffered, ldmatrix fragment loads,
// MMA schedule in 3 passes (hh / hl / lh) over 4 accumulators -> RAW distance 4.
//   Y[m][n] = sum_k A[m][k] * B[n][k]   (A,B as hi+lo f16, row stride = K)
// EPI 0: +bias[n] -> split f16 | 1: +bias[m] -> split f16
// EPI 2: *(*aux)  -> fp32      | 3: +res     -> fp32
// ============================================================================
template<int EPI>
__global__ __launch_bounds__(256, 2)
void hgemm_nt(const __half* __restrict__ Agh, const __half* __restrict__ Agl,
              const __half* __restrict__ Bgh, const __half* __restrict__ Bgl,
              const float* __restrict__ aux, const float* __restrict__ resg,
              float* __restrict__ Yfg, __half* __restrict__ Yhg, __half* __restrict__ Ylg,
              int K, int ldY, size_t strA, size_t strB, size_t strY)
{
    extern __shared__ char smem[];
    const uint32_t sb = smem_u32(smem);

    const int bz = blockIdx.z;
    const __half* Ah = Agh + strA * bz;
    const __half* Al = Agl + strA * bz;
    const __half* Bh = Bgh + strB * bz;
    const __half* Bl = Bgl + strB * bz;

    const int n0 = blockIdx.x * 128;
    const int m0 = blockIdx.y * 128;
    const int t    = threadIdx.x;
    const int lane = t & 31;
    const int warp = t >> 5;
    const int wm   = (warp & 3) * 32;
    const int wn   = (warp >> 2) * 64;
    const int grp  = lane >> 2;
    const int qid  = lane & 3;

    // ldmatrix per-lane byte offsets within a matrix tile
    const uint32_t offA = (uint32_t)(wm + (lane & 15)) * (PAD * 2) + (lane >> 4) * 16;
    const uint32_t offB = (uint32_t)(wn + ((lane >> 4) & 1) * 8 + (lane & 7)) * (PAD * 2)
                        + ((lane >> 3) & 1) * 16;

    float acc[2][8][4];
#pragma unroll
    for (int mt = 0; mt < 2; mt++)
#pragma unroll
        for (int nt = 0; nt < 8; nt++)
#pragma unroll
            for (int r = 0; r < 4; r++) acc[mt][nt][r] = 0.f;

    auto load_chunk = [&](int c) {
        const int k0 = c * BK;
        const uint32_t so = sb + (c & 1) * STG_B;
        const __half* srcs[4] = { Ah, Al, Bh, Bl };
#pragma unroll
        for (int mat = 0; mat < 4; mat++) {
            const __half* S = srcs[mat];
            const int base = (mat < 2) ? m0 : n0;
#pragma unroll
            for (int i = 0; i < 2; i++) {
                const int idx = t + 256 * i;
                const int kg = idx & 3, r = idx >> 2;
                cp16(so + mat * MAT_B + r * (PAD * 2) + kg * 16,
                     &S[(size_t)(base + r) * K + k0 + kg * 8]);
            }
        }
        cp_commit();
    };

    const int nch = K / BK;
    load_chunk(0);
    load_chunk(1);

    for (int c = 0; c < nch; c++) {
        if (c + 1 < nch) cp_wait<1>(); else cp_wait<0>();
        __syncthreads();

        const uint32_t stg = sb + (c & 1) * STG_B;
        const uint32_t aHb = stg;
        const uint32_t aLb = stg + MAT_B;
        const uint32_t bHb = stg + 2 * MAT_B;
        const uint32_t bLb = stg + 3 * MAT_B;

#pragma unroll
        for (int ks = 0; ks < 2; ks++) {
            const uint32_t kb2 = ks * 32;   // 16 halves = 32 bytes
            unsigned ah[2][4], al[2][4];
            ldsm4(ah[0], aHb + offA + kb2);
            ldsm4(ah[1], aHb + offA + 16 * (PAD * 2) + kb2);
            ldsm4(al[0], aLb + offA + kb2);
            ldsm4(al[1], aLb + offA + 16 * (PAD * 2) + kb2);
#pragma unroll
            for (int np = 0; np < 4; np++) {
                unsigned bh[4], bl[4];
                ldsm4(bh, bHb + offB + np * 16 * (PAD * 2) + kb2);
                ldsm4(bl, bLb + offB + np * 16 * (PAD * 2) + kb2);
                // pass 1: hi*hi — 4 distinct accumulators
                mma16816(acc[0][2 * np],     ah[0], bh[0], bh[1]);
                mma16816(acc[0][2 * np + 1], ah[0], bh[2], bh[3]);
                mma16816(acc[1][2 * np],     ah[1], bh[0], bh[1]);
                mma16816(acc[1][2 * np + 1], ah[1], bh[2], bh[3]);
                // pass 2: hi*lo
                mma16816(acc[0][2 * np],     ah[0], bl[0], bl[1]);
                mma16816(acc[0][2 * np + 1], ah[0], bl[2], bl[3]);
                mma16816(acc[1][2 * np],     ah[1], bl[0], bl[1]);
                mma16816(acc[1][2 * np + 1], ah[1], bl[2], bl[3]);
                // pass 3: lo*hi
                mma16816(acc[0][2 * np],     al[0], bh[0], bh[1]);
                mma16816(acc[0][2 * np + 1], al[0], bh[2], bh[3]);
                mma16816(acc[1][2 * np],     al[1], bh[0], bh[1]);
                mma16816(acc[1][2 * np + 1], al[1], bh[2], bh[3]);
            }
        }
        __syncthreads();
        if (c + 2 < nch) load_chunk(c + 2);
    }

    // ---- epilogue ----
    const float* res = (EPI == 3) ? (resg + strY * bz) : nullptr;
    float* Yf  = (EPI >= 2) ? (Yfg + strY * bz) : nullptr;
    __half* Yh = (EPI < 2) ? (Yhg + strY * bz) : nullptr;
    __half* Yl = (EPI < 2) ? (Ylg + strY * bz) : nullptr;
    const float sc = (EPI == 2) ? *aux : 0.f;

#pragma unroll
    for (int mt = 0; mt < 2; mt++)
#pragma unroll
        for (int r2 = 0; r2 < 2; r2++) {
            const int m = m0 + wm + mt * 16 + grp + 8 * r2;
            const float bvr = (EPI == 1) ? aux[m] : 0.f;
#pragma unroll
            for (int nt = 0; nt < 8; nt++) {
                const int n = n0 + wn + nt * 8 + qid * 2;
                float v0 = acc[mt][nt][r2 * 2 + 0];
                float v1 = acc[mt][nt][r2 * 2 + 1];
                if (EPI == 0) { v0 += aux[n]; v1 += aux[n + 1]; }
                if (EPI == 1) { v0 += bvr;    v1 += bvr; }
                if (EPI == 2) { v0 *= sc;     v1 *= sc; }
                const size_t off = (size_t)m * ldY + n;
                if (EPI == 3) { v0 += res[off]; v1 += res[off + 1]; }
                if (EPI >= 2) {
                    *(float2*)&Yf[off] = make_float2(v0, v1);
                } else {
                    __half h0, l0, h1, l1;
                    split2(v0, h0, l0); split2(v1, h1, l1);
                    *(__half2*)&Yh[off] = __halves2half2(h0, h1);
                    *(__half2*)&Yl[off] = __halves2half2(l0, l1);
                }
            }
        }
}

// ---------------- softmax over rows of S, emit split-f16 P -------------------
__global__ void softmax_split(const float* __restrict__ S,
                              __half* __restrict__ Ph, __half* __restrict__ Pl)
{
    __shared__ float red[256];
    const size_t ro = (size_t)blockIdx.x * NSP;
    const float* r = S + ro;
    const int t = threadIdx.x;

    float v[9];
    float mx = -1e30f;
#pragma unroll
    for (int i = 0; i < 9; i++) { v[i] = r[t + i * 256]; mx = fmaxf(mx, v[i]); }
    red[t] = mx;
    __syncthreads();
    for (int s = 128; s > 0; s >>= 1) {
        if (t < s) red[t] = fmaxf(red[t], red[t + s]);
        __syncthreads();
    }
    mx = red[0];
    __syncthreads();
    float sum = 0.f;
#pragma unroll
    for (int i = 0; i < 9; i++) { v[i] = __expf(v[i] - mx); sum += v[i]; }
    red[t] = sum;
    __syncthreads();
    for (int s = 128; s > 0; s >>= 1) {
        if (t < s) red[t] += red[t + s];
        __syncthreads();
    }
    const float inv = 1.0f / red[0];
#pragma unroll
    for (int i = 0; i < 9; i++) {
        __half h, l; split2(v[i] * inv, h, l);
        Ph[ro + t + i * 256] = h;
        Pl[ro + t + i * 256] = l;
    }
}

// ============================================================================
// Launch
// ============================================================================
extern "C" void kernel_launch(void* const* d_in, const int* in_sizes, int n_in,
                              void* d_out, int out_size)
{
    const float* img   = (const float*)d_in[0];
    const float* text  = (const float*)d_in[1];
    const float* w_tp  = (const float*)d_in[2];
    const float* b_tp  = (const float*)d_in[3];
    const float* w_q   = (const float*)d_in[4];
    const float* b_q   = (const float*)d_in[5];
    const float* w_k   = (const float*)d_in[6];
    const float* b_k   = (const float*)d_in[7];
    const float* w_v   = (const float*)d_in[8];
    const float* b_v   = (const float*)d_in[9];
    const float* scale = (const float*)d_in[10];

    __half *tTh, *tTl, *iTh, *iTl, *wh, *wl, *tfh, *tfl, *qh, *ql, *kh, *kl, *vh, *vl, *ph, *pl;
    float* sp;
    cudaGetSymbolAddress((void**)&tTh, g_tT_hi);  cudaGetSymbolAddress((void**)&tTl, g_tT_lo);
    cudaGetSymbolAddress((void**)&iTh, g_iT_hi);  cudaGetSymbolAddress((void**)&iTl, g_iT_lo);
    cudaGetSymbolAddress((void**)&wh,  g_w_hi);   cudaGetSymbolAddress((void**)&wl,  g_w_lo);
    cudaGetSymbolAddress((void**)&tfh, g_tfT_hi); cudaGetSymbolAddress((void**)&tfl, g_tfT_lo);
    cudaGetSymbolAddress((void**)&qh,  g_qT_hi);  cudaGetSymbolAddress((void**)&ql,  g_qT_lo);
    cudaGetSymbolAddress((void**)&kh,  g_kT_hi);  cudaGetSymbolAddress((void**)&kl,  g_kT_lo);
    cudaGetSymbolAddress((void**)&vh,  g_v_hi);   cudaGetSymbolAddress((void**)&vl,  g_v_lo);
    cudaGetSymbolAddress((void**)&ph,  g_P_hi);   cudaGetSymbolAddress((void**)&pl,  g_P_lo);
    cudaGetSymbolAddress((void**)&sp,  g_S);

    cudaFuncSetAttribute(hgemm_nt<0>, cudaFuncAttributeMaxDynamicSharedMemorySize, SMEM_TOTAL);
    cudaFuncSetAttribute(hgemm_nt<1>, cudaFuncAttributeMaxDynamicSharedMemorySize, SMEM_TOTAL);
    cudaFuncSetAttribute(hgemm_nt<2>, cudaFuncAttributeMaxDynamicSharedMemorySize, SMEM_TOTAL);
    cudaFuncSetAttribute(hgemm_nt<3>, cudaFuncAttributeMaxDynamicSharedMemorySize, SMEM_TOTAL);

    const size_t sNC = (size_t)NSP * CH;
    const size_t sNN = (size_t)NSP * NSP;
    const size_t sW  = (size_t)CH * CH;

    dim3 tb(32, 8);
    dim3 tg(NSP / 32, CH / 32, BATCH);
    split_transpose<<<tg, tb>>>(text, tTh, tTl);
    split_transpose<<<tg, tb>>>(img,  iTh, iTl);
    split_w<<<dim3(CH * CH / 256, 1, 4), 256>>>(w_tp, w_q, w_k, w_v, wh, wl);

    dim3 blk(256);
    dim3 grid_p (CH / 128, NSP / 128, BATCH);   // M=NSP, N=CH
    dim3 grid_v (NSP / 128, CH / 128, BATCH);   // M=CH,  N=NSP
    dim3 grid_s (NSP / 128, NSP / 128, BATCH);  // M=NSP, N=NSP

    // tfT[n][o] = text^T @ w_tp^T + b_tp
    hgemm_nt<0><<<grid_p, blk, SMEM_TOTAL>>>(tTh, tTl, wh, wl, b_tp, nullptr,
                                             nullptr, tfh, tfl, CH, CH, sNC, 0, sNC);
    // QT[n][o] = img^T @ w_q^T + b_q
    hgemm_nt<0><<<grid_p, blk, SMEM_TOTAL>>>(iTh, iTl, wh + sW, wl + sW, b_q, nullptr,
                                             nullptr, qh, ql, CH, CH, sNC, 0, sNC);
    // KT[n][o] = tfT @ w_k^T + b_k
    hgemm_nt<0><<<grid_p, blk, SMEM_TOTAL>>>(tfh, tfl, wh + 2 * sW, wl + 2 * sW, b_k, nullptr,
                                             nullptr, kh, kl, CH, CH, sNC, 0, sNC);
    // V[o][n] = w_v @ tf + b_v
    hgemm_nt<1><<<grid_v, blk, SMEM_TOTAL>>>(wh + 3 * sW, wl + 3 * sW, tfh, tfl, b_v, nullptr,
                                             nullptr, vh, vl, CH, NSP, 0, sNC, sNC);
    // S = scale * QT @ KT^T
    hgemm_nt<2><<<grid_s, blk, SMEM_TOTAL>>>(qh, ql, kh, kl, scale, nullptr,
                                             sp, nullptr, nullptr, CH, NSP, sNC, sNC, sNN);
    // P = softmax(S)
    softmax_split<<<BATCH * NSP, 256>>>(sp, ph, pl);
    // out = V @ P^T + img
    hgemm_nt<3><<<grid_v, blk, SMEM_TOTAL>>>(vh, vl, ph, pl, nullptr, img,
                                             (float*)d_out, nullptr, nullptr,
                                             NSP, NSP, sNC, sNN, sNC);
}